// round 1
// baseline (speedup 1.0000x reference)
#include <cuda_runtime.h>

#define BATCH 256

// ---------------- scratch (no allocations allowed) ----------------
__device__ unsigned char g_m1[BATCH * 64 * 64];
__device__ unsigned char g_m2[BATCH * 32 * 32];
__device__ unsigned char g_m3[BATCH * 32 * 32];
__device__ unsigned char g_m4[BATCH * 16 * 16];
__device__ float g_p1[BATCH * 32 * 32 * 32];   // [b][oc][32][32]
__device__ float g_p2[BATCH * 64 * 16 * 16];   // [b][oc][16][16] == flat
__device__ float g_h[BATCH * 128];

// ---------------- masks ----------------
__global__ void __launch_bounds__(256) masks_kernel(const int* __restrict__ cmap) {
    int b = blockIdx.x, t = threadIdx.x;
    __shared__ unsigned char cs[64 * 64];
    __shared__ unsigned char m1s[64 * 64];
    __shared__ unsigned char m2s[32 * 32];
    __shared__ unsigned char m3s[32 * 32];
    const int* cb = cmap + b * 4096;
    for (int i = t; i < 4096; i += 256) cs[i] = (unsigned char)cb[i];
    __syncthreads();
    for (int p = t; p < 4096; p += 256) {
        int i = p >> 6, j = p & 63;
        int s = 0;
        for (int di = 0; di < 3; di++) {
            int ii = i + di; if (ii >= 64) break;
            for (int dj = 0; dj < 3; dj++) {
                int jj = j + dj; if (jj >= 64) break;
                s += cs[(ii << 6) | jj];
            }
        }
        m1s[p] = (s > 1);
    }
    __syncthreads();
    for (int p = t; p < 4096; p += 256) g_m1[b * 4096 + p] = m1s[p];
    for (int p = t; p < 1024; p += 256) {
        int i = p >> 5, j = p & 31;
        int s = m1s[((2 * i) << 6) | (2 * j)] + m1s[((2 * i) << 6) | (2 * j + 1)]
              + m1s[((2 * i + 1) << 6) | (2 * j)] + m1s[((2 * i + 1) << 6) | (2 * j + 1)];
        m2s[p] = (s > 1);
    }
    __syncthreads();
    for (int p = t; p < 1024; p += 256) g_m2[b * 1024 + p] = m2s[p];
    for (int p = t; p < 1024; p += 256) {
        int i = p >> 5, j = p & 31;
        int s = 0;
        for (int di = 0; di < 3; di++) {
            int ii = i + di; if (ii >= 32) break;
            for (int dj = 0; dj < 3; dj++) {
                int jj = j + dj; if (jj >= 32) break;
                s += m2s[(ii << 5) | jj];
            }
        }
        m3s[p] = (s > 1);
    }
    __syncthreads();
    for (int p = t; p < 1024; p += 256) g_m3[b * 1024 + p] = m3s[p];
    for (int p = t; p < 256; p += 256) {
        int i = p >> 4, j = p & 15;
        int s = m3s[((2 * i) << 5) | (2 * j)] + m3s[((2 * i) << 5) | (2 * j + 1)]
              + m3s[((2 * i + 1) << 5) | (2 * j)] + m3s[((2 * i + 1) << 5) | (2 * j + 1)];
        g_m4[b * 256 + p] = (s > 1);
    }
}

// ---------------- conv1 + mask + relu + maxpool ----------------
__global__ void __launch_bounds__(256) conv1_kernel(const float* __restrict__ x,
                                                    const float* __restrict__ W1,
                                                    const float* __restrict__ b1) {
    int b = blockIdx.x, t = threadIdx.x;
    __shared__ float xs[64][65];
    __shared__ float W1s[32][9];
    __shared__ float b1s[32];
    __shared__ unsigned char m1s[4096];
    __shared__ unsigned char m2s[1024];
    const float* xb = x + b * 4096;
    for (int i = t; i < 4096; i += 256) xs[i >> 6][i & 63] = xb[i];
    for (int i = t; i < 288; i += 256) W1s[i / 9][i % 9] = W1[i];
    if (t < 32) b1s[t] = b1[t];
    for (int i = t; i < 4096; i += 256) m1s[i] = g_m1[b * 4096 + i];
    for (int i = t; i < 1024; i += 256) m2s[i] = g_m2[b * 1024 + i];
    __syncthreads();

    for (int p = t; p < 1024; p += 256) {
        int oi = p >> 5, oj = p & 31;
        float* out = g_p1 + (size_t)b * 32768 + oi * 32 + oj;  // + oc*1024
        if (!m2s[p]) {
            #pragma unroll 4
            for (int oc = 0; oc < 32; oc++) out[oc * 1024] = 0.f;
            continue;
        }
        float xv[4][4];
        int r0 = 2 * oi - 1, c0 = 2 * oj - 1;
        #pragma unroll
        for (int a = 0; a < 4; a++) {
            int r = r0 + a;
            #pragma unroll
            for (int c = 0; c < 4; c++) {
                int cc = c0 + c;
                xv[a][c] = (r >= 0 && r < 64 && cc >= 0 && cc < 64) ? xs[r][cc] : 0.f;
            }
        }
        float mm00 = m1s[((2 * oi) << 6) | (2 * oj)]     ? 1.f : 0.f;
        float mm01 = m1s[((2 * oi) << 6) | (2 * oj + 1)] ? 1.f : 0.f;
        float mm10 = m1s[((2 * oi + 1) << 6) | (2 * oj)] ? 1.f : 0.f;
        float mm11 = m1s[((2 * oi + 1) << 6) | (2 * oj + 1)] ? 1.f : 0.f;
        for (int oc = 0; oc < 32; oc++) {
            float a00 = 0.f, a01 = 0.f, a10 = 0.f, a11 = 0.f;
            #pragma unroll
            for (int di = 0; di < 3; di++)
                #pragma unroll
                for (int dj = 0; dj < 3; dj++) {
                    float w = W1s[oc][di * 3 + dj];
                    a00 += xv[di][dj] * w;
                    a01 += xv[di][dj + 1] * w;
                    a10 += xv[di + 1][dj] * w;
                    a11 += xv[di + 1][dj + 1] * w;
                }
            float bb = b1s[oc];
            float v = fmaxf(fmaxf(mm00 * fmaxf(a00 + bb, 0.f), mm01 * fmaxf(a01 + bb, 0.f)),
                            fmaxf(mm10 * fmaxf(a10 + bb, 0.f), mm11 * fmaxf(a11 + bb, 0.f)));
            out[oc * 1024] = v;
        }
    }
}

// ---------------- conv2 + mask + relu + maxpool ----------------
// smem: p1 padded [32][34][34] (36992 f) + W2 [288][68] oc-contig (19584 f) + b2 (64 f)
#define C2_SMEM_FLOATS (36992 + 19584 + 64)
__global__ void __launch_bounds__(512, 1) conv2_kernel(const float* __restrict__ W2,
                                                       const float* __restrict__ b2) {
    extern __shared__ float sm[];
    float* p1s = sm;            // 32*34*34
    float* W2s = sm + 36992;    // 288*68, layout [(ic*9+tap)*68 + oc]
    float* b2s = W2s + 19584;
    int b = blockIdx.x, t = threadIdx.x;

    for (int i = t; i < 36992; i += 512) p1s[i] = 0.f;
    for (int i = t; i < 18432; i += 512) {
        int oc = i / 288, q = i % 288;
        W2s[q * 68 + oc] = W2[i];
    }
    if (t < 64) b2s[t] = b2[t];
    __syncthreads();
    const float* p1b = g_p1 + (size_t)b * 32768;
    for (int i = t; i < 32768; i += 512) {
        int ic = i >> 10, r = (i >> 5) & 31, c = i & 31;
        p1s[ic * 1156 + (r + 1) * 34 + (c + 1)] = p1b[i];
    }
    __syncthreads();

    int warp = t >> 5, lane = t & 31;
    int ocg = lane >> 2, pg = lane & 3;
    const unsigned char* m3b = g_m3 + b * 1024;
    const unsigned char* m4b = g_m4 + b * 256;

    for (int iter = 0; iter < 2; iter++) {
        int wt = warp + 16 * iter;         // 0..31 warp-tasks
        int pr = wt >> 1, half = wt & 1;   // pooled row, col-half
        int cr0 = 2 * pr;                  // conv row base
        int cc0 = 16 * half + 4 * pg;      // conv col base (4 cols)

        float acc[8][8];
        #pragma unroll
        for (int o = 0; o < 8; o++)
            #pragma unroll
            for (int p = 0; p < 8; p++) acc[o][p] = 0.f;

        for (int ic = 0; ic < 32; ic++) {
            const float* xp = p1s + ic * 1156;
            const float* wp = W2s + ic * 9 * 68 + 8 * ocg;
            #pragma unroll
            for (int tap = 0; tap < 9; tap++) {
                const int di = tap / 3, dj = tap % 3;
                float4 w0 = *(const float4*)(wp + tap * 68);
                float4 w1 = *(const float4*)(wp + tap * 68 + 4);
                float wv[8] = {w0.x, w0.y, w0.z, w0.w, w1.x, w1.y, w1.z, w1.w};
                const float* xr = xp + (cr0 + di) * 34 + cc0 + dj;
                float xv[8];
                #pragma unroll
                for (int c = 0; c < 4; c++) { xv[c] = xr[c]; xv[4 + c] = xr[34 + c]; }
                #pragma unroll
                for (int o = 0; o < 8; o++)
                    #pragma unroll
                    for (int p = 0; p < 8; p++)
                        acc[o][p] += wv[o] * xv[p];
            }
        }

        // epilogue: gate by m3, +bias, relu, 2x2 pool, gate by m4
        float m3v[8];
        #pragma unroll
        for (int p = 0; p < 8; p++) {
            int a = p >> 2, c = p & 3;
            m3v[p] = m3b[(cr0 + a) * 32 + cc0 + c] ? 1.f : 0.f;
        }
        int pc0 = cc0 >> 1;
        float m4a = m4b[pr * 16 + pc0] ? 1.f : 0.f;
        float m4c = m4b[pr * 16 + pc0 + 1] ? 1.f : 0.f;
        #pragma unroll
        for (int o = 0; o < 8; o++) {
            int oc = 8 * ocg + o;
            float bb = b2s[oc];
            float pool0 = 0.f, pool1 = 0.f;
            #pragma unroll
            for (int p = 0; p < 8; p++) {
                float v = m3v[p] * fmaxf(acc[o][p] + bb, 0.f);
                if ((p & 3) < 2) pool0 = fmaxf(pool0, v);
                else             pool1 = fmaxf(pool1, v);
            }
            pool0 *= m4a;
            pool1 *= m4c;
            float* dst = g_p2 + (((size_t)b * 64 + oc) * 16 + pr) * 16 + pc0;
            dst[0] = pool0;
            dst[1] = pool1;
        }
    }
}

// ---------------- FC ----------------
__global__ void __launch_bounds__(256) fc_init_kernel(const float* __restrict__ bfc1) {
    int i = blockIdx.x * 256 + threadIdx.x;
    if (i < BATCH * 128) g_h[i] = bfc1[i & 127];
}

// grid (8 batch-tiles of 32, 16 k-chunks of 1024), 128 threads
__global__ void __launch_bounds__(128) fc1_kernel(const float* __restrict__ Wfc1) {
    __shared__ float As[32][36];   // [kk][brow]
    __shared__ float Ws[32][132];  // [kk][col]
    int bt = blockIdx.x;          // 0..7
    int kc = blockIdx.y;          // 0..15
    int t = threadIdx.x;
    int rg = t >> 4;              // 0..7  -> brow0 = 4*rg
    int cg = t & 15;              // 0..15 -> col0 = 8*cg
    float acc[4][8];
    #pragma unroll
    for (int i = 0; i < 4; i++)
        #pragma unroll
        for (int j = 0; j < 8; j++) acc[i][j] = 0.f;

    const float* flat = g_p2;  // [256][16384]
    int kbase = kc * 1024;
    for (int k0 = kbase; k0 < kbase + 1024; k0 += 32) {
        #pragma unroll
        for (int u = 0; u < 8; u++) {
            int idx = t + u * 128;
            int brow = idx >> 5, kk = idx & 31;
            As[kk][brow] = flat[(size_t)(bt * 32 + brow) * 16384 + k0 + kk];
        }
        #pragma unroll
        for (int u = 0; u < 32; u++) {
            int idx = t + u * 128;
            int kk = idx & 31, col = idx >> 5;
            Ws[kk][col] = Wfc1[(size_t)col * 16384 + k0 + kk];
        }
        __syncthreads();
        #pragma unroll
        for (int kk = 0; kk < 32; kk++) {
            float4 a = *(const float4*)&As[kk][4 * rg];
            float4 w0 = *(const float4*)&Ws[kk][8 * cg];
            float4 w1 = *(const float4*)&Ws[kk][8 * cg + 4];
            float av[4] = {a.x, a.y, a.z, a.w};
            float wv[8] = {w0.x, w0.y, w0.z, w0.w, w1.x, w1.y, w1.z, w1.w};
            #pragma unroll
            for (int i = 0; i < 4; i++)
                #pragma unroll
                for (int j = 0; j < 8; j++)
                    acc[i][j] += av[i] * wv[j];
        }
        __syncthreads();
    }
    #pragma unroll
    for (int i = 0; i < 4; i++)
        #pragma unroll
        for (int j = 0; j < 8; j++)
            atomicAdd(&g_h[(bt * 32 + 4 * rg + i) * 128 + 8 * cg + j], acc[i][j]);
}

__global__ void __launch_bounds__(128) fc2_kernel(const float* __restrict__ Wfc2,
                                                  const float* __restrict__ bfc2,
                                                  float* __restrict__ out) {
    int b = blockIdx.x, t = threadIdx.x;
    __shared__ float hr[128];
    hr[t] = fmaxf(g_h[b * 128 + t], 0.f);
    __syncthreads();
    if (t < 10) {
        float s = bfc2[t];
        const float* w = Wfc2 + t * 128;
        #pragma unroll 8
        for (int k = 0; k < 128; k++) s += hr[k] * w[k];
        out[b * 10 + t] = s;
    }
}

// ---------------- launch ----------------
extern "C" void kernel_launch(void* const* d_in, const int* in_sizes, int n_in,
                              void* d_out, int out_size) {
    const float* x    = (const float*)d_in[0];
    const int*   cmap = (const int*)  d_in[1];
    const float* W1   = (const float*)d_in[2];
    const float* b1   = (const float*)d_in[3];
    const float* W2   = (const float*)d_in[4];
    const float* b2   = (const float*)d_in[5];
    const float* Wfc1 = (const float*)d_in[6];
    const float* bfc1 = (const float*)d_in[7];
    const float* Wfc2 = (const float*)d_in[8];
    const float* bfc2 = (const float*)d_in[9];
    float* out = (float*)d_out;

    cudaFuncSetAttribute(conv2_kernel, cudaFuncAttributeMaxDynamicSharedMemorySize,
                         C2_SMEM_FLOATS * (int)sizeof(float));

    masks_kernel<<<BATCH, 256>>>(cmap);
    conv1_kernel<<<BATCH, 256>>>(x, W1, b1);
    conv2_kernel<<<BATCH, 512, C2_SMEM_FLOATS * sizeof(float)>>>(W2, b2);
    fc_init_kernel<<<(BATCH * 128 + 255) / 256, 256>>>(bfc1);
    dim3 g1(8, 16);
    fc1_kernel<<<g1, 128>>>(Wfc1);
    fc2_kernel<<<BATCH, 128>>>(Wfc2, bfc2, out);
}

// round 3
// speedup vs baseline: 1.0048x; 1.0048x over previous
#include <cuda_runtime.h>
#include <cuda_bf16.h>
#include <cstdint>

#define BATCH 256

// ---------------- scratch ----------------
__device__ unsigned char g_m1[BATCH * 4096];
__device__ unsigned char g_m2[BATCH * 1024];
__device__ unsigned char g_m3[BATCH * 1024];
__device__ unsigned char g_m4[BATCH * 256];
__device__ __align__(16) __nv_bfloat16 g_p1hi[BATCH * 34 * 34 * 32];
__device__ __align__(16) __nv_bfloat16 g_p1lo[BATCH * 34 * 34 * 32];
__device__ float g_p2[BATCH * 64 * 16 * 16];
__device__ float g_h[BATCH * 128];

// ---------------- helpers ----------------
static __device__ __forceinline__ uint32_t s2u(const void* p) {
    uint32_t a;
    asm("{ .reg .u64 t; cvta.to.shared.u64 t, %1; cvt.u32.u64 %0, t; }" : "=r"(a) : "l"(p));
    return a;
}
#define LDSM4(r, addr) \
    asm volatile("ldmatrix.sync.aligned.m8n8.x4.shared.b16 {%0,%1,%2,%3}, [%4];" \
        : "=r"((r)[0]), "=r"((r)[1]), "=r"((r)[2]), "=r"((r)[3]) : "r"(addr))
#define MMA16816(c, a, b0, b1) \
    asm volatile("mma.sync.aligned.m16n8k16.row.col.f32.bf16.bf16.f32 " \
        "{%0,%1,%2,%3}, {%4,%5,%6,%7}, {%8,%9}, {%0,%1,%2,%3};" \
        : "+f"((c)[0]), "+f"((c)[1]), "+f"((c)[2]), "+f"((c)[3]) \
        : "r"((a)[0]), "r"((a)[1]), "r"((a)[2]), "r"((a)[3]), "r"(b0), "r"(b1))

// ---------------- masks ----------------
__global__ void __launch_bounds__(256) masks_kernel(const int* __restrict__ cmap) {
    int b = blockIdx.x, t = threadIdx.x;
    __shared__ unsigned char cs[64 * 64];
    __shared__ unsigned char m1s[64 * 64];
    __shared__ unsigned char m2s[32 * 32];
    __shared__ unsigned char m3s[32 * 32];
    const int* cb = cmap + b * 4096;
    for (int i = t; i < 4096; i += 256) cs[i] = (unsigned char)cb[i];
    __syncthreads();
    for (int p = t; p < 4096; p += 256) {
        int i = p >> 6, j = p & 63;
        int s = 0;
        for (int di = 0; di < 3; di++) {
            int ii = i + di; if (ii >= 64) break;
            for (int dj = 0; dj < 3; dj++) {
                int jj = j + dj; if (jj >= 64) break;
                s += cs[(ii << 6) | jj];
            }
        }
        m1s[p] = (s > 1);
    }
    __syncthreads();
    for (int p = t; p < 4096; p += 256) g_m1[b * 4096 + p] = m1s[p];
    for (int p = t; p < 1024; p += 256) {
        int i = p >> 5, j = p & 31;
        int s = m1s[((2 * i) << 6) | (2 * j)] + m1s[((2 * i) << 6) | (2 * j + 1)]
              + m1s[((2 * i + 1) << 6) | (2 * j)] + m1s[((2 * i + 1) << 6) | (2 * j + 1)];
        m2s[p] = (s > 1);
    }
    __syncthreads();
    for (int p = t; p < 1024; p += 256) g_m2[b * 1024 + p] = m2s[p];
    for (int p = t; p < 1024; p += 256) {
        int i = p >> 5, j = p & 31;
        int s = 0;
        for (int di = 0; di < 3; di++) {
            int ii = i + di; if (ii >= 32) break;
            for (int dj = 0; dj < 3; dj++) {
                int jj = j + dj; if (jj >= 32) break;
                s += m2s[(ii << 5) | jj];
            }
        }
        m3s[p] = (s > 1);
    }
    __syncthreads();
    for (int p = t; p < 1024; p += 256) g_m3[b * 1024 + p] = m3s[p];
    for (int p = t; p < 256; p += 256) {
        int i = p >> 4, j = p & 15;
        int s = m3s[((2 * i) << 5) | (2 * j)] + m3s[((2 * i) << 5) | (2 * j + 1)]
              + m3s[((2 * i + 1) << 5) | (2 * j)] + m3s[((2 * i + 1) << 5) | (2 * j + 1)];
        g_m4[b * 256 + p] = (s > 1);
    }
}

// ---------------- p1 border zero (padded layout) ----------------
__global__ void __launch_bounds__(256) border_kernel() {
    int b = blockIdx.x, t = threadIdx.x;
    for (int i = t; i < 4224; i += 256) {
        int cl = i >> 5, ic = i & 31, row, col;
        if (cl < 34)       { row = 0;        col = cl; }
        else if (cl < 68)  { row = 33;       col = cl - 34; }
        else if (cl < 100) { row = cl - 67;  col = 0; }
        else               { row = cl - 99;  col = 33; }
        size_t idx = (((size_t)b * 34 + row) * 34 + col) * 32 + ic;
        g_p1hi[idx] = __float2bfloat16(0.f);
        g_p1lo[idx] = __float2bfloat16(0.f);
    }
}

// ---------------- conv1 + mask + relu + maxpool -> bf16 hi/lo padded ----------------
__global__ void __launch_bounds__(256) conv1_kernel(const float* __restrict__ x,
                                                    const float* __restrict__ W1,
                                                    const float* __restrict__ b1) {
    int b = blockIdx.x, t = threadIdx.x;
    __shared__ float xs[64][65];
    __shared__ float W1s[32][9];
    __shared__ float b1s[32];
    __shared__ unsigned char m1s[4096];
    __shared__ unsigned char m2s[1024];
    const float* xb = x + b * 4096;
    for (int i = t; i < 4096; i += 256) xs[i >> 6][i & 63] = xb[i];
    for (int i = t; i < 288; i += 256) W1s[i / 9][i % 9] = W1[i];
    if (t < 32) b1s[t] = b1[t];
    for (int i = t; i < 4096; i += 256) m1s[i] = g_m1[b * 4096 + i];
    for (int i = t; i < 1024; i += 256) m2s[i] = g_m2[b * 1024 + i];
    __syncthreads();

    for (int p = t; p < 1024; p += 256) {
        int oi = p >> 5, oj = p & 31;
        size_t pb = (((size_t)b * 34 + oi + 1) * 34 + (oj + 1)) * 32;
        if (!m2s[p]) {
            #pragma unroll 4
            for (int oc = 0; oc < 32; oc++) {
                g_p1hi[pb + oc] = __float2bfloat16(0.f);
                g_p1lo[pb + oc] = __float2bfloat16(0.f);
            }
            continue;
        }
        float xv[4][4];
        int r0 = 2 * oi - 1, c0 = 2 * oj - 1;
        #pragma unroll
        for (int a = 0; a < 4; a++) {
            int r = r0 + a;
            #pragma unroll
            for (int c = 0; c < 4; c++) {
                int cc = c0 + c;
                xv[a][c] = (r >= 0 && r < 64 && cc >= 0 && cc < 64) ? xs[r][cc] : 0.f;
            }
        }
        float mm00 = m1s[((2 * oi) << 6) | (2 * oj)]     ? 1.f : 0.f;
        float mm01 = m1s[((2 * oi) << 6) | (2 * oj + 1)] ? 1.f : 0.f;
        float mm10 = m1s[((2 * oi + 1) << 6) | (2 * oj)] ? 1.f : 0.f;
        float mm11 = m1s[((2 * oi + 1) << 6) | (2 * oj + 1)] ? 1.f : 0.f;
        for (int oc = 0; oc < 32; oc++) {
            float a00 = 0.f, a01 = 0.f, a10 = 0.f, a11 = 0.f;
            #pragma unroll
            for (int di = 0; di < 3; di++)
                #pragma unroll
                for (int dj = 0; dj < 3; dj++) {
                    float w = W1s[oc][di * 3 + dj];
                    a00 += xv[di][dj] * w;
                    a01 += xv[di][dj + 1] * w;
                    a10 += xv[di + 1][dj] * w;
                    a11 += xv[di + 1][dj + 1] * w;
                }
            float bb = b1s[oc];
            float v = fmaxf(fmaxf(mm00 * fmaxf(a00 + bb, 0.f), mm01 * fmaxf(a01 + bb, 0.f)),
                            fmaxf(mm10 * fmaxf(a10 + bb, 0.f), mm11 * fmaxf(a11 + bb, 0.f)));
            __nv_bfloat16 hi = __float2bfloat16(v);
            __nv_bfloat16 lo = __float2bfloat16(v - __bfloat162float(hi));
            g_p1hi[pb + oc] = hi;
            g_p1lo[pb + oc] = lo;
        }
    }
}

// ---------------- conv2 via mma.sync bf16 (3-term hi/lo split) ----------------
// smem layout (bytes):
//  SM_W     [term(2)][tap(9)][oc(64)] pitch 80B, ic*2 within  -> 92160
//  SM_STRIP [term(2)][10 rows][34 cols] px pitch 80B          -> 54400
//  SM_EX    256 px x 68-float pitch (fp32)                    -> 69632
#define SM_W     0
#define SM_STRIP 92160
#define SM_EX    146560
#define SM_B2    216192
#define SM_M3    216448
#define SM_M4    217472
#define C2_SMEM  217728

__global__ void __launch_bounds__(256, 1) conv2_mma_kernel(const float* __restrict__ W2,
                                                           const float* __restrict__ b2) {
    extern __shared__ char sm[];
    float* ex  = (float*)(sm + SM_EX);
    float* b2s = (float*)(sm + SM_B2);
    int t = threadIdx.x, b = blockIdx.x;
    int warp = t >> 5, lane = t & 31;
    uint32_t sb = s2u(sm);

    // W2 split into bf16 hi/lo, [term][tap][oc] rows (80B pitch), ic contiguous
    for (int i = t; i < 18432; i += 256) {
        int oc = i / 288, rem = i - oc * 288, ic = rem / 9, tap = rem - ic * 9;
        float v = W2[i];
        __nv_bfloat16 hi = __float2bfloat16(v);
        __nv_bfloat16 lo = __float2bfloat16(v - __bfloat162float(hi));
        int base = tap * 5120 + oc * 80 + ic * 2;
        *(__nv_bfloat16*)(sm + SM_W + base)         = hi;
        *(__nv_bfloat16*)(sm + SM_W + 46080 + base) = lo;
    }
    if (t < 64) b2s[t] = b2[t];
    for (int i = t; i < 1024; i += 256) sm[SM_M3 + i] = (char)g_m3[b * 1024 + i];
    if (t < 256) sm[SM_M4 + t] = (char)g_m4[b * 256 + t];
    __syncthreads();

    int wm = warp & 3, wn = warp >> 2;         // 4 M-quarters x 2 N-halves
    int g = lane >> 2, tig = lane & 3;
    int rowlane = lane & 15;
    int aKoff = (lane >= 16) ? 16 : 0;         // A: lanes 0-15 rows, 16-31 rows +16B (k8-15)
    int grpB = lane >> 3;
    int ocoffB = ((grpB >> 1) << 3) + (lane & 7);
    int bKoff = (grpB & 1) * 16;

    for (int mt = 0; mt < 4; mt++) {
        // load strip: padded rows 8mt..8mt+9 of p1 (hi+lo), re-pitch 64B -> 80B
        const uint4* shp = (const uint4*)g_p1hi + ((size_t)(b * 34 + 8 * mt) * 34) * 4;
        const uint4* slp = (const uint4*)g_p1lo + ((size_t)(b * 34 + 8 * mt) * 34) * 4;
        for (int i = t; i < 2720; i += 256) {
            int term = (i >= 1360), j = i - term * 1360;
            uint4 v = term ? slp[j] : shp[j];
            int px = j >> 2, q = j & 3;
            *(uint4*)(sm + SM_STRIP + term * 27200 + px * 80 + q * 16) = v;
        }
        __syncthreads();

        float acc[4][4][4];
        #pragma unroll
        for (int mi = 0; mi < 4; mi++)
            #pragma unroll
            for (int nt = 0; nt < 4; nt++)
                #pragma unroll
                for (int e = 0; e < 4; e++) acc[mi][nt][e] = 0.f;

        for (int tap = 0; tap < 9; tap++) {
            int di = tap / 3, dj = tap - di * 3;
            #pragma unroll
            for (int kc = 0; kc < 2; kc++) {
                uint32_t ah[4][4], al[4][4], bh[2][4], bl[2][4];
                #pragma unroll
                for (int mi = 0; mi < 4; mi++) {
                    int lr = 2 * wm + (mi >> 1);
                    int c0 = (mi & 1) * 16;
                    uint32_t addr = sb + SM_STRIP +
                        (uint32_t)(((lr + di) * 34 + c0 + rowlane + dj) * 80 + kc * 32 + aKoff);
                    LDSM4(ah[mi], addr);
                    LDSM4(al[mi], addr + 27200);
                }
                #pragma unroll
                for (int nb = 0; nb < 2; nb++) {
                    int oc0 = wn * 32 + nb * 16;
                    uint32_t baddr = sb + SM_W +
                        (uint32_t)(tap * 5120 + (oc0 + ocoffB) * 80 + kc * 32 + bKoff);
                    LDSM4(bh[nb], baddr);
                    LDSM4(bl[nb], baddr + 46080);
                }
                #pragma unroll
                for (int mi = 0; mi < 4; mi++)
                    #pragma unroll
                    for (int nt = 0; nt < 4; nt++) {
                        int nb = nt >> 1, sub = nt & 1;
                        uint32_t b0h = bh[nb][sub * 2], b1h = bh[nb][sub * 2 + 1];
                        uint32_t b0l = bl[nb][sub * 2], b1l = bl[nb][sub * 2 + 1];
                        MMA16816(acc[mi][nt], ah[mi], b0h, b1h);   // hi*hi
                        MMA16816(acc[mi][nt], al[mi], b0h, b1h);   // lo*hi
                        MMA16816(acc[mi][nt], ah[mi], b0l, b1l);   // hi*lo
                    }
            }
        }

        // write acc -> ex[px][oc] (pitch 68 floats)
        #pragma unroll
        for (int mi = 0; mi < 4; mi++)
            #pragma unroll
            for (int nt = 0; nt < 4; nt++) {
                int px0 = wm * 64 + mi * 16 + g;
                int oc = wn * 32 + nt * 8 + tig * 2;
                *(float2*)&ex[px0 * 68 + oc]       = make_float2(acc[mi][nt][0], acc[mi][nt][1]);
                *(float2*)&ex[(px0 + 8) * 68 + oc] = make_float2(acc[mi][nt][2], acc[mi][nt][3]);
            }
        __syncthreads();

        // epilogue: m3 gate, +bias, relu, 2x2 pool, m4 gate
        for (int i = t; i < 4096; i += 256) {
            int oc = i & 63, pl = i >> 6, pr = pl >> 4, pc = pl & 15;
            float bb = b2s[oc];
            float m = 0.f;
            #pragma unroll
            for (int dr = 0; dr < 2; dr++)
                #pragma unroll
                for (int dc = 0; dc < 2; dc++) {
                    int lr2 = 2 * pr + dr, c = 2 * pc + dc;
                    int px = lr2 * 32 + c;
                    float v = sm[SM_M3 + (8 * mt + lr2) * 32 + c]
                              ? fmaxf(ex[px * 68 + oc] + bb, 0.f) : 0.f;
                    m = fmaxf(m, v);
                }
            int prg = 4 * mt + pr;
            float m4v = sm[SM_M4 + prg * 16 + pc] ? 1.f : 0.f;
            g_p2[(((size_t)b * 64 + oc) * 16 + prg) * 16 + pc] = m * m4v;
        }
        __syncthreads();
    }
}

// ---------------- FC ----------------
__global__ void __launch_bounds__(256) fc_init_kernel(const float* __restrict__ bfc1) {
    int i = blockIdx.x * 256 + threadIdx.x;
    if (i < BATCH * 128) g_h[i] = bfc1[i & 127];
}

__global__ void __launch_bounds__(128) fc1_kernel(const float* __restrict__ Wfc1) {
    __shared__ float As[32][36];
    __shared__ float Ws[32][132];
    int bt = blockIdx.x;
    int kc = blockIdx.y;
    int t = threadIdx.x;
    int rg = t >> 4;
    int cg = t & 15;
    float acc[4][8];
    #pragma unroll
    for (int i = 0; i < 4; i++)
        #pragma unroll
        for (int j = 0; j < 8; j++) acc[i][j] = 0.f;

    const float* flat = g_p2;
    int kbase = kc * 1024;
    for (int k0 = kbase; k0 < kbase + 1024; k0 += 32) {
        #pragma unroll
        for (int u = 0; u < 8; u++) {
            int idx = t + u * 128;
            int brow = idx >> 5, kk = idx & 31;
            As[kk][brow] = flat[(size_t)(bt * 32 + brow) * 16384 + k0 + kk];
        }
        #pragma unroll
        for (int u = 0; u < 32; u++) {
            int idx = t + u * 128;
            int kk = idx & 31, col = idx >> 5;
            Ws[kk][col] = Wfc1[(size_t)col * 16384 + k0 + kk];
        }
        __syncthreads();
        #pragma unroll
        for (int kk = 0; kk < 32; kk++) {
            float4 a = *(const float4*)&As[kk][4 * rg];
            float4 w0 = *(const float4*)&Ws[kk][8 * cg];
            float4 w1 = *(const float4*)&Ws[kk][8 * cg + 4];
            float av[4] = {a.x, a.y, a.z, a.w};
            float wv[8] = {w0.x, w0.y, w0.z, w0.w, w1.x, w1.y, w1.z, w1.w};
            #pragma unroll
            for (int i = 0; i < 4; i++)
                #pragma unroll
                for (int j = 0; j < 8; j++)
                    acc[i][j] += av[i] * wv[j];
        }
        __syncthreads();
    }
    #pragma unroll
    for (int i = 0; i < 4; i++)
        #pragma unroll
        for (int j = 0; j < 8; j++)
            atomicAdd(&g_h[(bt * 32 + 4 * rg + i) * 128 + 8 * cg + j], acc[i][j]);
}

__global__ void __launch_bounds__(128) fc2_kernel(const float* __restrict__ Wfc2,
                                                  const float* __restrict__ bfc2,
                                                  float* __restrict__ out) {
    int b = blockIdx.x, t = threadIdx.x;
    __shared__ float hr[128];
    hr[t] = fmaxf(g_h[b * 128 + t], 0.f);
    __syncthreads();
    if (t < 10) {
        float s = bfc2[t];
        const float* w = Wfc2 + t * 128;
        #pragma unroll 8
        for (int k = 0; k < 128; k++) s += hr[k] * w[k];
        out[b * 10 + t] = s;
    }
}

// ---------------- launch ----------------
extern "C" void kernel_launch(void* const* d_in, const int* in_sizes, int n_in,
                              void* d_out, int out_size) {
    const float* x    = (const float*)d_in[0];
    const int*   cmap = (const int*)  d_in[1];
    const float* W1   = (const float*)d_in[2];
    const float* b1   = (const float*)d_in[3];
    const float* W2   = (const float*)d_in[4];
    const float* b2   = (const float*)d_in[5];
    const float* Wfc1 = (const float*)d_in[6];
    const float* bfc1 = (const float*)d_in[7];
    const float* Wfc2 = (const float*)d_in[8];
    const float* bfc2 = (const float*)d_in[9];
    float* out = (float*)d_out;

    cudaFuncSetAttribute(conv2_mma_kernel, cudaFuncAttributeMaxDynamicSharedMemorySize, C2_SMEM);

    masks_kernel<<<BATCH, 256>>>(cmap);
    border_kernel<<<BATCH, 256>>>();
    conv1_kernel<<<BATCH, 256>>>(x, W1, b1);
    conv2_mma_kernel<<<BATCH, 256, C2_SMEM>>>(W2, b2);
    fc_init_kernel<<<(BATCH * 128 + 255) / 256, 256>>>(bfc1);
    dim3 g1(8, 16);
    fc1_kernel<<<g1, 128>>>(Wfc1);
    fc2_kernel<<<BATCH, 128>>>(Wfc2, bfc2, out);
}

// round 4
// speedup vs baseline: 1.3812x; 1.3747x over previous
#include <cuda_runtime.h>
#include <cuda_bf16.h>
#include <cstdint>

#define BATCH 256

// ---------------- scratch ----------------
__device__ unsigned char g_m1[BATCH * 4096];
__device__ unsigned char g_m2[BATCH * 1024];
__device__ unsigned char g_m3[BATCH * 1024];
__device__ unsigned char g_m4[BATCH * 256];
__device__ __align__(16) __nv_bfloat16 g_p1hi[BATCH * 34 * 34 * 32];
__device__ __align__(16) __nv_bfloat16 g_p1lo[BATCH * 34 * 34 * 32];
__device__ float g_p2[BATCH * 64 * 16 * 16];
__device__ float g_h[BATCH * 128];

// ---------------- helpers ----------------
static __device__ __forceinline__ uint32_t s2u(const void* p) {
    uint32_t a;
    asm("{ .reg .u64 t; cvta.to.shared.u64 t, %1; cvt.u32.u64 %0, t; }" : "=r"(a) : "l"(p));
    return a;
}
#define LDSM4(r, addr) \
    asm volatile("ldmatrix.sync.aligned.m8n8.x4.shared.b16 {%0,%1,%2,%3}, [%4];" \
        : "=r"((r)[0]), "=r"((r)[1]), "=r"((r)[2]), "=r"((r)[3]) : "r"(addr))
#define MMA16816(c, a, b0, b1) \
    asm volatile("mma.sync.aligned.m16n8k16.row.col.f32.bf16.bf16.f32 " \
        "{%0,%1,%2,%3}, {%4,%5,%6,%7}, {%8,%9}, {%0,%1,%2,%3};" \
        : "+f"((c)[0]), "+f"((c)[1]), "+f"((c)[2]), "+f"((c)[3]) \
        : "r"((a)[0]), "r"((a)[1]), "r"((a)[2]), "r"((a)[3]), "r"(b0), "r"(b1))

// ---------------- masks ----------------
__global__ void __launch_bounds__(256) masks_kernel(const int* __restrict__ cmap) {
    int b = blockIdx.x, t = threadIdx.x;
    __shared__ unsigned char cs[64 * 64];
    __shared__ unsigned char m1s[64 * 64];
    __shared__ unsigned char m2s[32 * 32];
    __shared__ unsigned char m3s[32 * 32];
    const int* cb = cmap + b * 4096;
    for (int i = t; i < 4096; i += 256) cs[i] = (unsigned char)cb[i];
    __syncthreads();
    for (int p = t; p < 4096; p += 256) {
        int i = p >> 6, j = p & 63;
        int s = 0;
        for (int di = 0; di < 3; di++) {
            int ii = i + di; if (ii >= 64) break;
            for (int dj = 0; dj < 3; dj++) {
                int jj = j + dj; if (jj >= 64) break;
                s += cs[(ii << 6) | jj];
            }
        }
        m1s[p] = (s > 1);
    }
    __syncthreads();
    for (int p = t; p < 4096; p += 256) g_m1[b * 4096 + p] = m1s[p];
    for (int p = t; p < 1024; p += 256) {
        int i = p >> 5, j = p & 31;
        int s = m1s[((2 * i) << 6) | (2 * j)] + m1s[((2 * i) << 6) | (2 * j + 1)]
              + m1s[((2 * i + 1) << 6) | (2 * j)] + m1s[((2 * i + 1) << 6) | (2 * j + 1)];
        m2s[p] = (s > 1);
    }
    __syncthreads();
    for (int p = t; p < 1024; p += 256) g_m2[b * 1024 + p] = m2s[p];
    for (int p = t; p < 1024; p += 256) {
        int i = p >> 5, j = p & 31;
        int s = 0;
        for (int di = 0; di < 3; di++) {
            int ii = i + di; if (ii >= 32) break;
            for (int dj = 0; dj < 3; dj++) {
                int jj = j + dj; if (jj >= 32) break;
                s += m2s[(ii << 5) | jj];
            }
        }
        m3s[p] = (s > 1);
    }
    __syncthreads();
    for (int p = t; p < 1024; p += 256) g_m3[b * 1024 + p] = m3s[p];
    for (int p = t; p < 256; p += 256) {
        int i = p >> 4, j = p & 15;
        int s = m3s[((2 * i) << 5) | (2 * j)] + m3s[((2 * i) << 5) | (2 * j + 1)]
              + m3s[((2 * i + 1) << 5) | (2 * j)] + m3s[((2 * i + 1) << 5) | (2 * j + 1)];
        g_m4[b * 256 + p] = (s > 1);
    }
}

// ---------------- p1 border zero (vectorized) ----------------
__global__ void __launch_bounds__(256) border_kernel() {
    int b = blockIdx.x, t = threadIdx.x;
    const uint4 z = {0u, 0u, 0u, 0u};
    for (int i = t; i < 1056; i += 256) {
        int arr = (i >= 528);
        int j = i - arr * 528;
        int q = j & 3, cl = j >> 2;
        int row, col;
        if (cl < 34)       { row = 0;        col = cl; }
        else if (cl < 68)  { row = 33;       col = cl - 34; }
        else if (cl < 100) { row = cl - 67;  col = 0; }
        else               { row = cl - 99;  col = 33; }
        uint4* dst = arr ? (uint4*)g_p1lo : (uint4*)g_p1hi;
        dst[((size_t)(b * 34 + row) * 34 + col) * 4 + q] = z;
    }
}

// ---------------- conv1 + mask + relu + maxpool -> bf16 hi/lo (coalesced) ----------------
// dynamic smem layout (bytes):
//  0      xs     64x65 f32           16640
//  16640  W1s    288 f32             1152
//  17792  b1s    32 f32              128
//  17920  m1s    4096 u8
//  22016  m2s    1024 u8
//  23040  hbuf   512 px x 17 u32     34816
//  57856  lbuf   512 px x 17 u32     34816
//  total 92672
#define C1_SMEM 92672
__global__ void __launch_bounds__(256, 2) conv1_kernel(const float* __restrict__ x,
                                                       const float* __restrict__ W1,
                                                       const float* __restrict__ b1) {
    extern __shared__ char sm1[];
    float* xs  = (float*)sm1;                     // pitch 65
    float* W1s = (float*)(sm1 + 16640);
    float* b1s = (float*)(sm1 + 17792);
    unsigned char* m1s = (unsigned char*)(sm1 + 17920);
    unsigned char* m2s = (unsigned char*)(sm1 + 22016);
    uint32_t* hbuf = (uint32_t*)(sm1 + 23040);    // [512][17] (16 used + 1 pad)
    uint32_t* lbuf = (uint32_t*)(sm1 + 57856);
    int b = blockIdx.x, t = threadIdx.x;

    const float* xb = x + b * 4096;
    for (int i = t; i < 4096; i += 256) xs[(i >> 6) * 65 + (i & 63)] = xb[i];
    for (int i = t; i < 288; i += 256) W1s[i] = W1[i];
    if (t < 32) b1s[t] = b1[t];
    for (int i = t; i < 4096; i += 256) m1s[i] = g_m1[b * 4096 + i];
    for (int i = t; i < 1024; i += 256) m2s[i] = g_m2[b * 1024 + i];
    __syncthreads();

    uint32_t* ghi = (uint32_t*)g_p1hi;
    uint32_t* glo = (uint32_t*)g_p1lo;

    for (int half = 0; half < 2; half++) {
        #pragma unroll
        for (int pp = 0; pp < 2; pp++) {
            int lp = pp * 256 + t;                 // 0..511 local px
            int p  = half * 512 + lp;
            int oi = p >> 5, oj = p & 31;
            if (!m2s[p]) {
                #pragma unroll
                for (int k = 0; k < 16; k++) { hbuf[lp * 17 + k] = 0u; lbuf[lp * 17 + k] = 0u; }
                continue;
            }
            float xv[4][4];
            int r0 = 2 * oi - 1, c0 = 2 * oj - 1;
            #pragma unroll
            for (int a = 0; a < 4; a++) {
                int r = r0 + a;
                #pragma unroll
                for (int c = 0; c < 4; c++) {
                    int cc = c0 + c;
                    xv[a][c] = (r >= 0 && r < 64 && cc >= 0 && cc < 64) ? xs[r * 65 + cc] : 0.f;
                }
            }
            float mm00 = m1s[((2 * oi) << 6) | (2 * oj)]     ? 1.f : 0.f;
            float mm01 = m1s[((2 * oi) << 6) | (2 * oj + 1)] ? 1.f : 0.f;
            float mm10 = m1s[((2 * oi + 1) << 6) | (2 * oj)] ? 1.f : 0.f;
            float mm11 = m1s[((2 * oi + 1) << 6) | (2 * oj + 1)] ? 1.f : 0.f;
            uint32_t hw = 0, lw = 0;
            for (int oc = 0; oc < 32; oc++) {
                float a00 = 0.f, a01 = 0.f, a10 = 0.f, a11 = 0.f;
                #pragma unroll
                for (int di = 0; di < 3; di++)
                    #pragma unroll
                    for (int dj = 0; dj < 3; dj++) {
                        float w = W1s[oc * 9 + di * 3 + dj];
                        a00 += xv[di][dj] * w;
                        a01 += xv[di][dj + 1] * w;
                        a10 += xv[di + 1][dj] * w;
                        a11 += xv[di + 1][dj + 1] * w;
                    }
                float bb = b1s[oc];
                float v = fmaxf(fmaxf(mm00 * fmaxf(a00 + bb, 0.f), mm01 * fmaxf(a01 + bb, 0.f)),
                                fmaxf(mm10 * fmaxf(a10 + bb, 0.f), mm11 * fmaxf(a11 + bb, 0.f)));
                __nv_bfloat16 hb = __float2bfloat16(v);
                float lov = v - __bfloat162float(hb);
                __nv_bfloat16 lb = __float2bfloat16(lov);
                uint32_t hu = (uint32_t)__bfloat16_as_ushort(hb);
                uint32_t lu = (uint32_t)__bfloat16_as_ushort(lb);
                if (oc & 1) {
                    hw |= hu << 16; lw |= lu << 16;
                    hbuf[lp * 17 + (oc >> 1)] = hw;
                    lbuf[lp * 17 + (oc >> 1)] = lw;
                } else { hw = hu; lw = lu; }
            }
        }
        __syncthreads();
        // coalesced copy-out: 512 px x 16 words -> padded global rows
        for (int i = t; i < 8192; i += 256) {
            int px = i >> 4, w = i & 15;
            int oi = half * 16 + (px >> 5), oj = px & 31;
            size_t dst = ((size_t)(b * 34 + oi + 1) * 34 + oj + 1) * 16 + w;
            ghi[dst] = hbuf[px * 17 + w];
            glo[dst] = lbuf[px * 17 + w];
        }
        __syncthreads();
    }
}

// ---------------- conv2 via mma.sync bf16 (3-term hi/lo split, 16 warps) ----------------
#define SM_W     0
#define SM_STRIP 92160
#define SM_EX    146560
#define SM_B2    216192
#define SM_M3    216448
#define SM_M4    217472
#define C2_SMEM  217728

__global__ void __launch_bounds__(512, 1) conv2_mma_kernel(const float* __restrict__ W2,
                                                           const float* __restrict__ b2) {
    extern __shared__ char sm[];
    float* ex  = (float*)(sm + SM_EX);
    float* b2s = (float*)(sm + SM_B2);
    int t = threadIdx.x, b = blockIdx.x;
    int warp = t >> 5, lane = t & 31;
    uint32_t sb = s2u(sm);

    // W2 split into bf16 hi/lo, [term][tap][oc] rows (80B pitch), ic contiguous
    for (int i = t; i < 18432; i += 512) {
        int oc = i / 288, rem = i - oc * 288, ic = rem / 9, tap = rem - ic * 9;
        float v = W2[i];
        __nv_bfloat16 hi = __float2bfloat16(v);
        __nv_bfloat16 lo = __float2bfloat16(v - __bfloat162float(hi));
        int base = tap * 5120 + oc * 80 + ic * 2;
        *(__nv_bfloat16*)(sm + SM_W + base)         = hi;
        *(__nv_bfloat16*)(sm + SM_W + 46080 + base) = lo;
    }
    if (t < 64) b2s[t] = b2[t];
    for (int i = t; i < 1024; i += 512) sm[SM_M3 + i] = (char)g_m3[b * 1024 + i];
    if (t < 256) sm[SM_M4 + t] = (char)g_m4[b * 256 + t];
    __syncthreads();

    int wm = warp & 3, wn = warp >> 2;         // 4 M-quarters x 4 N-sixteenths
    int g = lane >> 2, tig = lane & 3;
    int rowlane = lane & 15;
    int aKoff = (lane >= 16) ? 16 : 0;
    int grpB = lane >> 3;
    int ocoffB = ((grpB >> 1) << 3) + (lane & 7);
    int bKoff = (grpB & 1) * 16;
    int oc0 = wn * 16;

    for (int mt = 0; mt < 4; mt++) {
        // load strip: padded rows 8mt..8mt+9 of p1 (hi+lo), re-pitch 64B -> 80B
        const uint4* shp = (const uint4*)g_p1hi + ((size_t)(b * 34 + 8 * mt) * 34) * 4;
        const uint4* slp = (const uint4*)g_p1lo + ((size_t)(b * 34 + 8 * mt) * 34) * 4;
        for (int i = t; i < 2720; i += 512) {
            int term = (i >= 1360), j = i - term * 1360;
            uint4 v = term ? slp[j] : shp[j];
            int px = j >> 2, q = j & 3;
            *(uint4*)(sm + SM_STRIP + term * 27200 + px * 80 + q * 16) = v;
        }
        __syncthreads();

        float acc[4][2][4];
        #pragma unroll
        for (int mi = 0; mi < 4; mi++)
            #pragma unroll
            for (int nt = 0; nt < 2; nt++)
                #pragma unroll
                for (int e = 0; e < 4; e++) acc[mi][nt][e] = 0.f;

        for (int tap = 0; tap < 9; tap++) {
            int di = tap / 3, dj = tap - di * 3;
            #pragma unroll
            for (int kc = 0; kc < 2; kc++) {
                uint32_t ah[4][4], al[4][4], bh[4], bl[4];
                #pragma unroll
                for (int mi = 0; mi < 4; mi++) {
                    int lr = 2 * wm + (mi >> 1);
                    int c0 = (mi & 1) * 16;
                    uint32_t addr = sb + SM_STRIP +
                        (uint32_t)(((lr + di) * 34 + c0 + rowlane + dj) * 80 + kc * 32 + aKoff);
                    LDSM4(ah[mi], addr);
                    LDSM4(al[mi], addr + 27200);
                }
                {
                    uint32_t baddr = sb + SM_W +
                        (uint32_t)(tap * 5120 + (oc0 + ocoffB) * 80 + kc * 32 + bKoff);
                    LDSM4(bh, baddr);
                    LDSM4(bl, baddr + 46080);
                }
                #pragma unroll
                for (int mi = 0; mi < 4; mi++)
                    #pragma unroll
                    for (int nt = 0; nt < 2; nt++) {
                        uint32_t b0h = bh[nt * 2], b1h = bh[nt * 2 + 1];
                        uint32_t b0l = bl[nt * 2], b1l = bl[nt * 2 + 1];
                        MMA16816(acc[mi][nt], ah[mi], b0h, b1h);   // hi*hi
                        MMA16816(acc[mi][nt], al[mi], b0h, b1h);   // lo*hi
                        MMA16816(acc[mi][nt], ah[mi], b0l, b1l);   // hi*lo
                    }
            }
        }

        // write acc -> ex[px][oc] (pitch 68 floats)
        #pragma unroll
        for (int mi = 0; mi < 4; mi++)
            #pragma unroll
            for (int nt = 0; nt < 2; nt++) {
                int px0 = wm * 64 + mi * 16 + g;
                int oc = oc0 + nt * 8 + tig * 2;
                *(float2*)&ex[px0 * 68 + oc]       = make_float2(acc[mi][nt][0], acc[mi][nt][1]);
                *(float2*)&ex[(px0 + 8) * 68 + oc] = make_float2(acc[mi][nt][2], acc[mi][nt][3]);
            }
        __syncthreads();

        // epilogue: m3 gate, +bias, relu, 2x2 pool, m4 gate
        for (int i = t; i < 4096; i += 512) {
            int oc = i & 63, pl = i >> 6, pr = pl >> 4, pc = pl & 15;
            float bb = b2s[oc];
            float m = 0.f;
            #pragma unroll
            for (int dr = 0; dr < 2; dr++)
                #pragma unroll
                for (int dc = 0; dc < 2; dc++) {
                    int lr2 = 2 * pr + dr, c = 2 * pc + dc;
                    int px = lr2 * 32 + c;
                    float v = sm[SM_M3 + (8 * mt + lr2) * 32 + c]
                              ? fmaxf(ex[px * 68 + oc] + bb, 0.f) : 0.f;
                    m = fmaxf(m, v);
                }
            int prg = 4 * mt + pr;
            float m4v = sm[SM_M4 + prg * 16 + pc] ? 1.f : 0.f;
            g_p2[(((size_t)b * 64 + oc) * 16 + prg) * 16 + pc] = m * m4v;
        }
        __syncthreads();
    }
}

// ---------------- FC ----------------
__global__ void __launch_bounds__(256) fc_init_kernel(const float* __restrict__ bfc1) {
    int i = blockIdx.x * 256 + threadIdx.x;
    if (i < BATCH * 128) g_h[i] = bfc1[i & 127];
}

// grid (8 batch-tiles of 32, 64 k-chunks of 256), 128 threads
__global__ void __launch_bounds__(128) fc1_kernel(const float* __restrict__ Wfc1) {
    __shared__ float As[32][36];
    __shared__ float Ws[32][132];
    int bt = blockIdx.x;
    int kc = blockIdx.y;
    int t = threadIdx.x;
    int rg = t >> 4;
    int cg = t & 15;
    float acc[4][8];
    #pragma unroll
    for (int i = 0; i < 4; i++)
        #pragma unroll
        for (int j = 0; j < 8; j++) acc[i][j] = 0.f;

    const float* flat = g_p2;
    int kbase = kc * 256;
    for (int k0 = kbase; k0 < kbase + 256; k0 += 32) {
        #pragma unroll
        for (int u = 0; u < 8; u++) {
            int idx = t + u * 128;
            int brow = idx >> 5, kk = idx & 31;
            As[kk][brow] = flat[(size_t)(bt * 32 + brow) * 16384 + k0 + kk];
        }
        #pragma unroll
        for (int u = 0; u < 32; u++) {
            int idx = t + u * 128;
            int kk = idx & 31, col = idx >> 5;
            Ws[kk][col] = Wfc1[(size_t)col * 16384 + k0 + kk];
        }
        __syncthreads();
        #pragma unroll
        for (int kk = 0; kk < 32; kk++) {
            float4 a = *(const float4*)&As[kk][4 * rg];
            float4 w0 = *(const float4*)&Ws[kk][8 * cg];
            float4 w1 = *(const float4*)&Ws[kk][8 * cg + 4];
            float av[4] = {a.x, a.y, a.z, a.w};
            float wv[8] = {w0.x, w0.y, w0.z, w0.w, w1.x, w1.y, w1.z, w1.w};
            #pragma unroll
            for (int i = 0; i < 4; i++)
                #pragma unroll
                for (int j = 0; j < 8; j++)
                    acc[i][j] += av[i] * wv[j];
        }
        __syncthreads();
    }
    #pragma unroll
    for (int i = 0; i < 4; i++)
        #pragma unroll
        for (int j = 0; j < 8; j++)
            atomicAdd(&g_h[(bt * 32 + 4 * rg + i) * 128 + 8 * cg + j], acc[i][j]);
}

__global__ void __launch_bounds__(128) fc2_kernel(const float* __restrict__ Wfc2,
                                                  const float* __restrict__ bfc2,
                                                  float* __restrict__ out) {
    int b = blockIdx.x, t = threadIdx.x;
    __shared__ float hr[128];
    hr[t] = fmaxf(g_h[b * 128 + t], 0.f);
    __syncthreads();
    if (t < 10) {
        float s = bfc2[t];
        const float* w = Wfc2 + t * 128;
        #pragma unroll 8
        for (int k = 0; k < 128; k++) s += hr[k] * w[k];
        out[b * 10 + t] = s;
    }
}

// ---------------- launch ----------------
extern "C" void kernel_launch(void* const* d_in, const int* in_sizes, int n_in,
                              void* d_out, int out_size) {
    const float* x    = (const float*)d_in[0];
    const int*   cmap = (const int*)  d_in[1];
    const float* W1   = (const float*)d_in[2];
    const float* b1   = (const float*)d_in[3];
    const float* W2   = (const float*)d_in[4];
    const float* b2   = (const float*)d_in[5];
    const float* Wfc1 = (const float*)d_in[6];
    const float* bfc1 = (const float*)d_in[7];
    const float* Wfc2 = (const float*)d_in[8];
    const float* bfc2 = (const float*)d_in[9];
    float* out = (float*)d_out;

    cudaFuncSetAttribute(conv1_kernel, cudaFuncAttributeMaxDynamicSharedMemorySize, C1_SMEM);
    cudaFuncSetAttribute(conv2_mma_kernel, cudaFuncAttributeMaxDynamicSharedMemorySize, C2_SMEM);

    masks_kernel<<<BATCH, 256>>>(cmap);
    border_kernel<<<BATCH, 256>>>();
    conv1_kernel<<<BATCH, 256, C1_SMEM>>>(x, W1, b1);
    conv2_mma_kernel<<<BATCH, 512, C2_SMEM>>>(W2, b2);
    fc_init_kernel<<<(BATCH * 128 + 255) / 256, 256>>>(bfc1);
    dim3 g1(8, 64);
    fc1_kernel<<<g1, 128>>>(Wfc1);
    fc2_kernel<<<BATCH, 128>>>(Wfc2, bfc2, out);
}

// round 5
// speedup vs baseline: 1.5128x; 1.0952x over previous
#include <cuda_runtime.h>
#include <cuda_fp16.h>
#include <cstdint>

#define BATCH 256

// ---------------- scratch ----------------
__device__ unsigned char g_m1[BATCH * 4096];
__device__ unsigned char g_m2[BATCH * 1024];
__device__ unsigned char g_m3[BATCH * 1024];
__device__ unsigned char g_m4[BATCH * 256];
__device__ __align__(16) __half g_p1hi[BATCH * 34 * 34 * 32];
__device__ __align__(16) __half g_p1lo[BATCH * 34 * 34 * 32];
__device__ float g_p2[BATCH * 64 * 16 * 16];
__device__ float g_h[BATCH * 128];

// ---------------- helpers ----------------
static __device__ __forceinline__ uint32_t s2u(const void* p) {
    uint32_t a;
    asm("{ .reg .u64 t; cvta.to.shared.u64 t, %1; cvt.u32.u64 %0, t; }" : "=r"(a) : "l"(p));
    return a;
}
#define LDSM4(r, addr) \
    asm volatile("ldmatrix.sync.aligned.m8n8.x4.shared.b16 {%0,%1,%2,%3}, [%4];" \
        : "=r"((r)[0]), "=r"((r)[1]), "=r"((r)[2]), "=r"((r)[3]) : "r"(addr))
#define MMA16816F(c, a, b0, b1) \
    asm volatile("mma.sync.aligned.m16n8k16.row.col.f32.f16.f16.f32 " \
        "{%0,%1,%2,%3}, {%4,%5,%6,%7}, {%8,%9}, {%0,%1,%2,%3};" \
        : "+f"((c)[0]), "+f"((c)[1]), "+f"((c)[2]), "+f"((c)[3]) \
        : "r"((a)[0]), "r"((a)[1]), "r"((a)[2]), "r"((a)[3]), "r"(b0), "r"(b1))

// ---------------- masks ----------------
__global__ void __launch_bounds__(256) masks_kernel(const int* __restrict__ cmap) {
    int b = blockIdx.x, t = threadIdx.x;
    __shared__ unsigned char cs[64 * 64];
    __shared__ unsigned char m1s[64 * 64];
    __shared__ unsigned char m2s[32 * 32];
    __shared__ unsigned char m3s[32 * 32];
    const int* cb = cmap + b * 4096;
    for (int i = t; i < 4096; i += 256) cs[i] = (unsigned char)cb[i];
    __syncthreads();
    for (int p = t; p < 4096; p += 256) {
        int i = p >> 6, j = p & 63;
        int s = 0;
        for (int di = 0; di < 3; di++) {
            int ii = i + di; if (ii >= 64) break;
            for (int dj = 0; dj < 3; dj++) {
                int jj = j + dj; if (jj >= 64) break;
                s += cs[(ii << 6) | jj];
            }
        }
        m1s[p] = (s > 1);
    }
    __syncthreads();
    for (int p = t; p < 4096; p += 256) g_m1[b * 4096 + p] = m1s[p];
    for (int p = t; p < 1024; p += 256) {
        int i = p >> 5, j = p & 31;
        int s = m1s[((2 * i) << 6) | (2 * j)] + m1s[((2 * i) << 6) | (2 * j + 1)]
              + m1s[((2 * i + 1) << 6) | (2 * j)] + m1s[((2 * i + 1) << 6) | (2 * j + 1)];
        m2s[p] = (s > 1);
    }
    __syncthreads();
    for (int p = t; p < 1024; p += 256) g_m2[b * 1024 + p] = m2s[p];
    for (int p = t; p < 1024; p += 256) {
        int i = p >> 5, j = p & 31;
        int s = 0;
        for (int di = 0; di < 3; di++) {
            int ii = i + di; if (ii >= 32) break;
            for (int dj = 0; dj < 3; dj++) {
                int jj = j + dj; if (jj >= 32) break;
                s += m2s[(ii << 5) | jj];
            }
        }
        m3s[p] = (s > 1);
    }
    __syncthreads();
    for (int p = t; p < 1024; p += 256) g_m3[b * 1024 + p] = m3s[p];
    for (int p = t; p < 256; p += 256) {
        int i = p >> 4, j = p & 15;
        int s = m3s[((2 * i) << 5) | (2 * j)] + m3s[((2 * i) << 5) | (2 * j + 1)]
              + m3s[((2 * i + 1) << 5) | (2 * j)] + m3s[((2 * i + 1) << 5) | (2 * j + 1)];
        g_m4[b * 256 + p] = (s > 1);
    }
}

// ---------------- p1 border zero (vectorized) ----------------
__global__ void __launch_bounds__(256) border_kernel() {
    int b = blockIdx.x, t = threadIdx.x;
    const uint4 z = {0u, 0u, 0u, 0u};
    for (int i = t; i < 1056; i += 256) {
        int arr = (i >= 528);
        int j = i - arr * 528;
        int q = j & 3, cl = j >> 2;
        int row, col;
        if (cl < 34)       { row = 0;        col = cl; }
        else if (cl < 68)  { row = 33;       col = cl - 34; }
        else if (cl < 100) { row = cl - 67;  col = 0; }
        else               { row = cl - 99;  col = 33; }
        uint4* dst = arr ? (uint4*)g_p1lo : (uint4*)g_p1hi;
        dst[((size_t)(b * 34 + row) * 34 + col) * 4 + q] = z;
    }
}

// ---------------- conv1 + mask + relu + maxpool -> fp16 hi/lo (coalesced) ----------------
#define C1_SMEM 92672
__global__ void __launch_bounds__(256, 2) conv1_kernel(const float* __restrict__ x,
                                                       const float* __restrict__ W1,
                                                       const float* __restrict__ b1) {
    extern __shared__ char sm1[];
    float* xs  = (float*)sm1;                     // pitch 65
    float* W1s = (float*)(sm1 + 16640);
    float* b1s = (float*)(sm1 + 17792);
    unsigned char* m1s = (unsigned char*)(sm1 + 17920);
    unsigned char* m2s = (unsigned char*)(sm1 + 22016);
    uint32_t* hbuf = (uint32_t*)(sm1 + 23040);    // [512][17]
    uint32_t* lbuf = (uint32_t*)(sm1 + 57856);
    int b = blockIdx.x, t = threadIdx.x;

    const float* xb = x + b * 4096;
    for (int i = t; i < 4096; i += 256) xs[(i >> 6) * 65 + (i & 63)] = xb[i];
    for (int i = t; i < 288; i += 256) W1s[i] = W1[i];
    if (t < 32) b1s[t] = b1[t];
    for (int i = t; i < 4096; i += 256) m1s[i] = g_m1[b * 4096 + i];
    for (int i = t; i < 1024; i += 256) m2s[i] = g_m2[b * 1024 + i];
    __syncthreads();

    uint32_t* ghi = (uint32_t*)g_p1hi;
    uint32_t* glo = (uint32_t*)g_p1lo;

    for (int half = 0; half < 2; half++) {
        #pragma unroll
        for (int pp = 0; pp < 2; pp++) {
            int lp = pp * 256 + t;
            int p  = half * 512 + lp;
            int oi = p >> 5, oj = p & 31;
            if (!m2s[p]) {
                #pragma unroll
                for (int k = 0; k < 16; k++) { hbuf[lp * 17 + k] = 0u; lbuf[lp * 17 + k] = 0u; }
                continue;
            }
            float xv[4][4];
            int r0 = 2 * oi - 1, c0 = 2 * oj - 1;
            #pragma unroll
            for (int a = 0; a < 4; a++) {
                int r = r0 + a;
                #pragma unroll
                for (int c = 0; c < 4; c++) {
                    int cc = c0 + c;
                    xv[a][c] = (r >= 0 && r < 64 && cc >= 0 && cc < 64) ? xs[r * 65 + cc] : 0.f;
                }
            }
            float mm00 = m1s[((2 * oi) << 6) | (2 * oj)]     ? 1.f : 0.f;
            float mm01 = m1s[((2 * oi) << 6) | (2 * oj + 1)] ? 1.f : 0.f;
            float mm10 = m1s[((2 * oi + 1) << 6) | (2 * oj)] ? 1.f : 0.f;
            float mm11 = m1s[((2 * oi + 1) << 6) | (2 * oj + 1)] ? 1.f : 0.f;
            uint32_t hw = 0, lw = 0;
            for (int oc = 0; oc < 32; oc++) {
                float a00 = 0.f, a01 = 0.f, a10 = 0.f, a11 = 0.f;
                #pragma unroll
                for (int di = 0; di < 3; di++)
                    #pragma unroll
                    for (int dj = 0; dj < 3; dj++) {
                        float w = W1s[oc * 9 + di * 3 + dj];
                        a00 += xv[di][dj] * w;
                        a01 += xv[di][dj + 1] * w;
                        a10 += xv[di + 1][dj] * w;
                        a11 += xv[di + 1][dj + 1] * w;
                    }
                float bb = b1s[oc];
                float v = fmaxf(fmaxf(mm00 * fmaxf(a00 + bb, 0.f), mm01 * fmaxf(a01 + bb, 0.f)),
                                fmaxf(mm10 * fmaxf(a10 + bb, 0.f), mm11 * fmaxf(a11 + bb, 0.f)));
                __half hb = __float2half_rn(v);
                float lov = v - __half2float(hb);
                __half lb = __float2half_rn(lov);
                uint32_t hu = (uint32_t)__half_as_ushort(hb);
                uint32_t lu = (uint32_t)__half_as_ushort(lb);
                if (oc & 1) {
                    hw |= hu << 16; lw |= lu << 16;
                    hbuf[lp * 17 + (oc >> 1)] = hw;
                    lbuf[lp * 17 + (oc >> 1)] = lw;
                } else { hw = hu; lw = lu; }
            }
        }
        __syncthreads();
        for (int i = t; i < 8192; i += 256) {
            int px = i >> 4, w = i & 15;
            int oi = half * 16 + (px >> 5), oj = px & 31;
            size_t dst = ((size_t)(b * 34 + oi + 1) * 34 + oj + 1) * 16 + w;
            ghi[dst] = hbuf[px * 17 + w];
            glo[dst] = lbuf[px * 17 + w];
        }
        __syncthreads();
    }
}

// ---------------- conv2 via mma.sync fp16 (2-term hi/lo split) ----------------
// smem layout (bytes):
//  SM_W     [tap(9)][oc(64)] pitch 80B (hi only)  -> 46080
//  SM_STRIP [term(2)][10 rows][34 cols] px 80B    -> 54400
//  SM_EX    256 px x 68-float pitch (fp32)        -> 69632
#define SM_W     0
#define SM_STRIP 46080
#define SM_EX    100480
#define SM_B2    170112
#define SM_M3    170368
#define SM_M4    171392
#define C2_SMEM  171648

__global__ void __launch_bounds__(512, 1) conv2_mma_kernel(const float* __restrict__ W2,
                                                           const float* __restrict__ b2) {
    extern __shared__ char sm[];
    float* ex  = (float*)(sm + SM_EX);
    float* b2s = (float*)(sm + SM_B2);
    int t = threadIdx.x, b = blockIdx.x;
    int warp = t >> 5, lane = t & 31;
    uint32_t sb = s2u(sm);

    // W2 -> fp16 (hi only), [tap][oc] rows (80B pitch), ic contiguous
    for (int i = t; i < 18432; i += 512) {
        int oc = i / 288, rem = i - oc * 288, ic = rem / 9, tap = rem - ic * 9;
        *(__half*)(sm + SM_W + tap * 5120 + oc * 80 + ic * 2) = __float2half_rn(W2[i]);
    }
    if (t < 64) b2s[t] = b2[t];
    for (int i = t; i < 1024; i += 512) sm[SM_M3 + i] = (char)g_m3[b * 1024 + i];
    if (t < 256) sm[SM_M4 + t] = (char)g_m4[b * 256 + t];
    __syncthreads();

    int wm = warp & 3, wn = warp >> 2;         // 4 M-quarters x 4 N-sixteenths
    int g = lane >> 2, tig = lane & 3;
    int rowlane = lane & 15;
    int aKoff = (lane >= 16) ? 16 : 0;
    int grpB = lane >> 3;
    int ocoffB = ((grpB >> 1) << 3) + (lane & 7);
    int bKoff = (grpB & 1) * 16;
    int oc0 = wn * 16;

    for (int mt = 0; mt < 4; mt++) {
        const uint4* shp = (const uint4*)g_p1hi + ((size_t)(b * 34 + 8 * mt) * 34) * 4;
        const uint4* slp = (const uint4*)g_p1lo + ((size_t)(b * 34 + 8 * mt) * 34) * 4;
        for (int i = t; i < 2720; i += 512) {
            int term = (i >= 1360), j = i - term * 1360;
            uint4 v = term ? slp[j] : shp[j];
            int px = j >> 2, q = j & 3;
            *(uint4*)(sm + SM_STRIP + term * 27200 + px * 80 + q * 16) = v;
        }
        __syncthreads();

        float acc[4][2][4];
        #pragma unroll
        for (int mi = 0; mi < 4; mi++)
            #pragma unroll
            for (int nt = 0; nt < 2; nt++)
                #pragma unroll
                for (int e = 0; e < 4; e++) acc[mi][nt][e] = 0.f;

        for (int tap = 0; tap < 9; tap++) {
            int di = tap / 3, dj = tap - di * 3;
            #pragma unroll
            for (int kc = 0; kc < 2; kc++) {
                uint32_t ah[4][4], al[4][4], bh[4];
                #pragma unroll
                for (int mi = 0; mi < 4; mi++) {
                    int lr = 2 * wm + (mi >> 1);
                    int c0 = (mi & 1) * 16;
                    uint32_t addr = sb + SM_STRIP +
                        (uint32_t)(((lr + di) * 34 + c0 + rowlane + dj) * 80 + kc * 32 + aKoff);
                    LDSM4(ah[mi], addr);
                    LDSM4(al[mi], addr + 27200);
                }
                {
                    uint32_t baddr = sb + SM_W +
                        (uint32_t)(tap * 5120 + (oc0 + ocoffB) * 80 + kc * 32 + bKoff);
                    LDSM4(bh, baddr);
                }
                #pragma unroll
                for (int mi = 0; mi < 4; mi++)
                    #pragma unroll
                    for (int nt = 0; nt < 2; nt++) {
                        uint32_t b0h = bh[nt * 2], b1h = bh[nt * 2 + 1];
                        MMA16816F(acc[mi][nt], ah[mi], b0h, b1h);   // hi*w
                        MMA16816F(acc[mi][nt], al[mi], b0h, b1h);   // lo*w
                    }
            }
        }

        // write acc -> ex[px][oc] (pitch 68 floats)
        #pragma unroll
        for (int mi = 0; mi < 4; mi++)
            #pragma unroll
            for (int nt = 0; nt < 2; nt++) {
                int px0 = wm * 64 + mi * 16 + g;
                int oc = oc0 + nt * 8 + tig * 2;
                *(float2*)&ex[px0 * 68 + oc]       = make_float2(acc[mi][nt][0], acc[mi][nt][1]);
                *(float2*)&ex[(px0 + 8) * 68 + oc] = make_float2(acc[mi][nt][2], acc[mi][nt][3]);
            }
        __syncthreads();

        // epilogue: m3 gate, +bias, relu, 2x2 pool, m4 gate
        for (int i = t; i < 4096; i += 512) {
            int oc = i & 63, pl = i >> 6, pr = pl >> 4, pc = pl & 15;
            float bb = b2s[oc];
            float m = 0.f;
            #pragma unroll
            for (int dr = 0; dr < 2; dr++)
                #pragma unroll
                for (int dc = 0; dc < 2; dc++) {
                    int lr2 = 2 * pr + dr, c = 2 * pc + dc;
                    int px = lr2 * 32 + c;
                    float v = sm[SM_M3 + (8 * mt + lr2) * 32 + c]
                              ? fmaxf(ex[px * 68 + oc] + bb, 0.f) : 0.f;
                    m = fmaxf(m, v);
                }
            int prg = 4 * mt + pr;
            float m4v = sm[SM_M4 + prg * 16 + pc] ? 1.f : 0.f;
            g_p2[(((size_t)b * 64 + oc) * 16 + prg) * 16 + pc] = m * m4v;
        }
        __syncthreads();
    }
}

// ---------------- FC ----------------
__global__ void __launch_bounds__(256) fc_init_kernel(const float* __restrict__ bfc1) {
    int i = blockIdx.x * 256 + threadIdx.x;
    if (i < BATCH * 128) g_h[i] = bfc1[i & 127];
}

// grid (8 batch-tiles of 32, 64 k-chunks of 256), 128 threads
__global__ void __launch_bounds__(128) fc1_kernel(const float* __restrict__ Wfc1) {
    __shared__ float As[32][36];
    __shared__ float Ws[32][132];
    int bt = blockIdx.x;
    int kc = blockIdx.y;
    int t = threadIdx.x;
    int rg = t >> 4;
    int cg = t & 15;
    float acc[4][8];
    #pragma unroll
    for (int i = 0; i < 4; i++)
        #pragma unroll
        for (int j = 0; j < 8; j++) acc[i][j] = 0.f;

    const float* flat = g_p2;
    int kbase = kc * 256;
    for (int k0 = kbase; k0 < kbase + 256; k0 += 32) {
        #pragma unroll
        for (int u = 0; u < 8; u++) {
            int idx = t + u * 128;
            int brow = idx >> 5, kk = idx & 31;
            As[kk][brow] = flat[(size_t)(bt * 32 + brow) * 16384 + k0 + kk];
        }
        #pragma unroll
        for (int u = 0; u < 32; u++) {
            int idx = t + u * 128;
            int kk = idx & 31, col = idx >> 5;
            Ws[kk][col] = Wfc1[(size_t)col * 16384 + k0 + kk];
        }
        __syncthreads();
        #pragma unroll
        for (int kk = 0; kk < 32; kk++) {
            float4 a = *(const float4*)&As[kk][4 * rg];
            float4 w0 = *(const float4*)&Ws[kk][8 * cg];
            float4 w1 = *(const float4*)&Ws[kk][8 * cg + 4];
            float av[4] = {a.x, a.y, a.z, a.w};
            float wv[8] = {w0.x, w0.y, w0.z, w0.w, w1.x, w1.y, w1.z, w1.w};
            #pragma unroll
            for (int i = 0; i < 4; i++)
                #pragma unroll
                for (int j = 0; j < 8; j++)
                    acc[i][j] += av[i] * wv[j];
        }
        __syncthreads();
    }
    #pragma unroll
    for (int i = 0; i < 4; i++)
        #pragma unroll
        for (int j = 0; j < 8; j++)
            atomicAdd(&g_h[(bt * 32 + 4 * rg + i) * 128 + 8 * cg + j], acc[i][j]);
}

__global__ void __launch_bounds__(128) fc2_kernel(const float* __restrict__ Wfc2,
                                                  const float* __restrict__ bfc2,
                                                  float* __restrict__ out) {
    int b = blockIdx.x, t = threadIdx.x;
    __shared__ float hr[128];
    hr[t] = fmaxf(g_h[b * 128 + t], 0.f);
    __syncthreads();
    if (t < 10) {
        float s = bfc2[t];
        const float* w = Wfc2 + t * 128;
        #pragma unroll 8
        for (int k = 0; k < 128; k++) s += hr[k] * w[k];
        out[b * 10 + t] = s;
    }
}

// ---------------- launch ----------------
extern "C" void kernel_launch(void* const* d_in, const int* in_sizes, int n_in,
                              void* d_out, int out_size) {
    const float* x    = (const float*)d_in[0];
    const int*   cmap = (const int*)  d_in[1];
    const float* W1   = (const float*)d_in[2];
    const float* b1   = (const float*)d_in[3];
    const float* W2   = (const float*)d_in[4];
    const float* b2   = (const float*)d_in[5];
    const float* Wfc1 = (const float*)d_in[6];
    const float* bfc1 = (const float*)d_in[7];
    const float* Wfc2 = (const float*)d_in[8];
    const float* bfc2 = (const float*)d_in[9];
    float* out = (float*)d_out;

    cudaFuncSetAttribute(conv1_kernel, cudaFuncAttributeMaxDynamicSharedMemorySize, C1_SMEM);
    cudaFuncSetAttribute(conv2_mma_kernel, cudaFuncAttributeMaxDynamicSharedMemorySize, C2_SMEM);

    masks_kernel<<<BATCH, 256>>>(cmap);
    border_kernel<<<BATCH, 256>>>();
    conv1_kernel<<<BATCH, 256, C1_SMEM>>>(x, W1, b1);
    conv2_mma_kernel<<<BATCH, 512, C2_SMEM>>>(W2, b2);
    fc_init_kernel<<<(BATCH * 128 + 255) / 256, 256>>>(bfc1);
    dim3 g1(8, 64);
    fc1_kernel<<<g1, 128>>>(Wfc1);
    fc2_kernel<<<BATCH, 128>>>(Wfc2, bfc2, out);
}

// round 6
// speedup vs baseline: 2.0469x; 1.3531x over previous
#include <cuda_runtime.h>
#include <cuda_fp16.h>
#include <cstdint>

#define BATCH 256

// ---------------- scratch ----------------
__device__ unsigned char g_m1[BATCH * 4096];
__device__ unsigned char g_m2[BATCH * 1024];
__device__ unsigned char g_m3[BATCH * 1024];
__device__ unsigned char g_m4[BATCH * 256];
__device__ __align__(16) __half g_p1hi[BATCH * 34 * 34 * 32];
__device__ __align__(16) __half g_p1lo[BATCH * 34 * 34 * 32];
__device__ __align__(16) __half g_p2h[BATCH * 16384];
__device__ __align__(16) __half g_p2l[BATCH * 16384];
__device__ float g_h[BATCH * 128];

// ---------------- helpers ----------------
static __device__ __forceinline__ uint32_t s2u(const void* p) {
    uint32_t a;
    asm("{ .reg .u64 t; cvta.to.shared.u64 t, %1; cvt.u32.u64 %0, t; }" : "=r"(a) : "l"(p));
    return a;
}
#define LDSM4(r, addr) \
    asm volatile("ldmatrix.sync.aligned.m8n8.x4.shared.b16 {%0,%1,%2,%3}, [%4];" \
        : "=r"((r)[0]), "=r"((r)[1]), "=r"((r)[2]), "=r"((r)[3]) : "r"(addr))
#define MMA16816F(c, a, b0, b1) \
    asm volatile("mma.sync.aligned.m16n8k16.row.col.f32.f16.f16.f32 " \
        "{%0,%1,%2,%3}, {%4,%5,%6,%7}, {%8,%9}, {%0,%1,%2,%3};" \
        : "+f"((c)[0]), "+f"((c)[1]), "+f"((c)[2]), "+f"((c)[3]) \
        : "r"((a)[0]), "r"((a)[1]), "r"((a)[2]), "r"((a)[3]), "r"(b0), "r"(b1))

// ---------------- masks ----------------
__global__ void __launch_bounds__(256) masks_kernel(const int* __restrict__ cmap) {
    int b = blockIdx.x, t = threadIdx.x;
    __shared__ unsigned char cs[64 * 64];
    __shared__ unsigned char m1s[64 * 64];
    __shared__ unsigned char m2s[32 * 32];
    __shared__ unsigned char m3s[32 * 32];
    const int* cb = cmap + b * 4096;
    for (int i = t; i < 4096; i += 256) cs[i] = (unsigned char)cb[i];
    __syncthreads();
    for (int p = t; p < 4096; p += 256) {
        int i = p >> 6, j = p & 63;
        int s = 0;
        for (int di = 0; di < 3; di++) {
            int ii = i + di; if (ii >= 64) break;
            for (int dj = 0; dj < 3; dj++) {
                int jj = j + dj; if (jj >= 64) break;
                s += cs[(ii << 6) | jj];
            }
        }
        m1s[p] = (s > 1);
    }
    __syncthreads();
    for (int p = t; p < 4096; p += 256) g_m1[b * 4096 + p] = m1s[p];
    for (int p = t; p < 1024; p += 256) {
        int i = p >> 5, j = p & 31;
        int s = m1s[((2 * i) << 6) | (2 * j)] + m1s[((2 * i) << 6) | (2 * j + 1)]
              + m1s[((2 * i + 1) << 6) | (2 * j)] + m1s[((2 * i + 1) << 6) | (2 * j + 1)];
        m2s[p] = (s > 1);
    }
    __syncthreads();
    for (int p = t; p < 1024; p += 256) g_m2[b * 1024 + p] = m2s[p];
    for (int p = t; p < 1024; p += 256) {
        int i = p >> 5, j = p & 31;
        int s = 0;
        for (int di = 0; di < 3; di++) {
            int ii = i + di; if (ii >= 32) break;
            for (int dj = 0; dj < 3; dj++) {
                int jj = j + dj; if (jj >= 32) break;
                s += m2s[(ii << 5) | jj];
            }
        }
        m3s[p] = (s > 1);
    }
    __syncthreads();
    for (int p = t; p < 1024; p += 256) g_m3[b * 1024 + p] = m3s[p];
    for (int p = t; p < 256; p += 256) {
        int i = p >> 4, j = p & 15;
        int s = m3s[((2 * i) << 5) | (2 * j)] + m3s[((2 * i) << 5) | (2 * j + 1)]
              + m3s[((2 * i + 1) << 5) | (2 * j)] + m3s[((2 * i + 1) << 5) | (2 * j + 1)];
        g_m4[b * 256 + p] = (s > 1);
    }
}

// ---------------- p1 border zero (vectorized) ----------------
__global__ void __launch_bounds__(256) border_kernel() {
    int b = blockIdx.x, t = threadIdx.x;
    const uint4 z = {0u, 0u, 0u, 0u};
    for (int i = t; i < 1056; i += 256) {
        int arr = (i >= 528);
        int j = i - arr * 528;
        int q = j & 3, cl = j >> 2;
        int row, col;
        if (cl < 34)       { row = 0;        col = cl; }
        else if (cl < 68)  { row = 33;       col = cl - 34; }
        else if (cl < 100) { row = cl - 67;  col = 0; }
        else               { row = cl - 99;  col = 33; }
        uint4* dst = arr ? (uint4*)g_p1lo : (uint4*)g_p1hi;
        dst[((size_t)(b * 34 + row) * 34 + col) * 4 + q] = z;
    }
}

// ---------------- conv1 + mask + relu + maxpool -> fp16 hi/lo (coalesced) ----------------
#define C1_SMEM 92672
__global__ void __launch_bounds__(256, 2) conv1_kernel(const float* __restrict__ x,
                                                       const float* __restrict__ W1,
                                                       const float* __restrict__ b1) {
    extern __shared__ char sm1[];
    float* xs  = (float*)sm1;                     // pitch 65
    float* W1s = (float*)(sm1 + 16640);
    float* b1s = (float*)(sm1 + 17792);
    unsigned char* m1s = (unsigned char*)(sm1 + 17920);
    unsigned char* m2s = (unsigned char*)(sm1 + 22016);
    uint32_t* hbuf = (uint32_t*)(sm1 + 23040);    // [512][17]
    uint32_t* lbuf = (uint32_t*)(sm1 + 57856);
    int b = blockIdx.x, t = threadIdx.x;

    const float* xb = x + b * 4096;
    for (int i = t; i < 4096; i += 256) xs[(i >> 6) * 65 + (i & 63)] = xb[i];
    for (int i = t; i < 288; i += 256) W1s[i] = W1[i];
    if (t < 32) b1s[t] = b1[t];
    for (int i = t; i < 4096; i += 256) m1s[i] = g_m1[b * 4096 + i];
    for (int i = t; i < 1024; i += 256) m2s[i] = g_m2[b * 1024 + i];
    __syncthreads();

    uint32_t* ghi = (uint32_t*)g_p1hi;
    uint32_t* glo = (uint32_t*)g_p1lo;

    for (int half = 0; half < 2; half++) {
        #pragma unroll
        for (int pp = 0; pp < 2; pp++) {
            int lp = pp * 256 + t;
            int p  = half * 512 + lp;
            int oi = p >> 5, oj = p & 31;
            if (!m2s[p]) {
                #pragma unroll
                for (int k = 0; k < 16; k++) { hbuf[lp * 17 + k] = 0u; lbuf[lp * 17 + k] = 0u; }
                continue;
            }
            float xv[4][4];
            int r0 = 2 * oi - 1, c0 = 2 * oj - 1;
            #pragma unroll
            for (int a = 0; a < 4; a++) {
                int r = r0 + a;
                #pragma unroll
                for (int c = 0; c < 4; c++) {
                    int cc = c0 + c;
                    xv[a][c] = (r >= 0 && r < 64 && cc >= 0 && cc < 64) ? xs[r * 65 + cc] : 0.f;
                }
            }
            float mm00 = m1s[((2 * oi) << 6) | (2 * oj)]     ? 1.f : 0.f;
            float mm01 = m1s[((2 * oi) << 6) | (2 * oj + 1)] ? 1.f : 0.f;
            float mm10 = m1s[((2 * oi + 1) << 6) | (2 * oj)] ? 1.f : 0.f;
            float mm11 = m1s[((2 * oi + 1) << 6) | (2 * oj + 1)] ? 1.f : 0.f;
            uint32_t hw = 0, lw = 0;
            for (int oc = 0; oc < 32; oc++) {
                float a00 = 0.f, a01 = 0.f, a10 = 0.f, a11 = 0.f;
                #pragma unroll
                for (int di = 0; di < 3; di++)
                    #pragma unroll
                    for (int dj = 0; dj < 3; dj++) {
                        float w = W1s[oc * 9 + di * 3 + dj];
                        a00 += xv[di][dj] * w;
                        a01 += xv[di][dj + 1] * w;
                        a10 += xv[di + 1][dj] * w;
                        a11 += xv[di + 1][dj + 1] * w;
                    }
                float bb = b1s[oc];
                float v = fmaxf(fmaxf(mm00 * fmaxf(a00 + bb, 0.f), mm01 * fmaxf(a01 + bb, 0.f)),
                                fmaxf(mm10 * fmaxf(a10 + bb, 0.f), mm11 * fmaxf(a11 + bb, 0.f)));
                __half hb = __float2half_rn(v);
                float lov = v - __half2float(hb);
                __half lb = __float2half_rn(lov);
                uint32_t hu = (uint32_t)__half_as_ushort(hb);
                uint32_t lu = (uint32_t)__half_as_ushort(lb);
                if (oc & 1) {
                    hw |= hu << 16; lw |= lu << 16;
                    hbuf[lp * 17 + (oc >> 1)] = hw;
                    lbuf[lp * 17 + (oc >> 1)] = lw;
                } else { hw = hu; lw = lu; }
            }
        }
        __syncthreads();
        for (int i = t; i < 8192; i += 256) {
            int px = i >> 4, w = i & 15;
            int oi = half * 16 + (px >> 5), oj = px & 31;
            size_t dst = ((size_t)(b * 34 + oi + 1) * 34 + oj + 1) * 16 + w;
            ghi[dst] = hbuf[px * 17 + w];
            glo[dst] = lbuf[px * 17 + w];
        }
        __syncthreads();
    }
}

// ---------------- conv2 via mma.sync fp16 (2-term, 256 thr, 2 CTAs/image) ----------------
// smem: W 46080 | strip 2x27200=54400 | b2 256 | m3 1024 | m4 256  => 102016 (2 CTAs/SM)
#define SM_W     0
#define SM_STRIP 46080
#define SM_B2    100480
#define SM_M3    100736
#define SM_M4    101760
#define C2_SMEM  102016

__global__ void __launch_bounds__(256, 2) conv2_mma_kernel(const float* __restrict__ W2,
                                                           const float* __restrict__ b2) {
    extern __shared__ char sm[];
    float* b2s = (float*)(sm + SM_B2);
    int t = threadIdx.x;
    int b = blockIdx.x >> 1, hf = blockIdx.x & 1;
    int warp = t >> 5, lane = t & 31;
    uint32_t sb = s2u(sm);

    // W2 -> fp16 (hi only), [tap][oc] rows (80B pitch), ic contiguous
    for (int i = t; i < 18432; i += 256) {
        int oc = i / 288, rem = i - oc * 288, ic = rem / 9, tap = rem - ic * 9;
        *(__half*)(sm + SM_W + tap * 5120 + oc * 80 + ic * 2) = __float2half_rn(W2[i]);
    }
    if (t < 64) b2s[t] = b2[t];
    for (int i = t; i < 1024; i += 256) sm[SM_M3 + i] = (char)g_m3[b * 1024 + i];
    sm[SM_M4 + t] = (char)g_m4[b * 256 + t];

    int wm = warp & 3, wn = warp >> 2;   // 4 M x 2 N(32oc)
    int oc0 = wn * 32;
    int g = lane >> 2, qu = lane & 3;
    int rowlane = lane & 15;
    int aKoff = (lane >= 16) ? 16 : 0;
    int grpB = lane >> 3;
    int ocoffB = ((grpB >> 1) << 3) + (lane & 7);
    int bKoff = (grpB & 1) * 16;

    for (int it = 0; it < 2; it++) {
        int mt = hf * 2 + it;
        __syncthreads();
        const uint4* shp = (const uint4*)g_p1hi + ((size_t)(b * 34 + 8 * mt) * 34) * 4;
        const uint4* slp = (const uint4*)g_p1lo + ((size_t)(b * 34 + 8 * mt) * 34) * 4;
        for (int i = t; i < 2720; i += 256) {
            int term = (i >= 1360), j = i - term * 1360;
            uint4 v = term ? slp[j] : shp[j];
            int px = j >> 2, q = j & 3;
            *(uint4*)(sm + SM_STRIP + term * 27200 + px * 80 + q * 16) = v;
        }
        __syncthreads();

        float acc[4][4][4];
        #pragma unroll
        for (int mi = 0; mi < 4; mi++)
            #pragma unroll
            for (int nt = 0; nt < 4; nt++)
                #pragma unroll
                for (int e = 0; e < 4; e++) acc[mi][nt][e] = 0.f;

        for (int tap = 0; tap < 9; tap++) {
            int di = tap / 3, dj = tap - di * 3;
            #pragma unroll
            for (int kc = 0; kc < 2; kc++) {
                uint32_t ah[4][4], al[4][4];
                #pragma unroll
                for (int mi = 0; mi < 4; mi++) {
                    int lr = 2 * wm + (mi >> 1);
                    int c0 = (mi & 1) * 16;
                    uint32_t addr = sb + SM_STRIP +
                        (uint32_t)(((lr + di) * 34 + c0 + rowlane + dj) * 80 + kc * 32 + aKoff);
                    LDSM4(ah[mi], addr);
                    LDSM4(al[mi], addr + 27200);
                }
                #pragma unroll
                for (int nb = 0; nb < 2; nb++) {
                    uint32_t bh[4];
                    uint32_t baddr = sb + SM_W +
                        (uint32_t)(tap * 5120 + (oc0 + nb * 16 + ocoffB) * 80 + kc * 32 + bKoff);
                    LDSM4(bh, baddr);
                    #pragma unroll
                    for (int mi = 0; mi < 4; mi++)
                        #pragma unroll
                        for (int s2 = 0; s2 < 2; s2++) {
                            int nt = nb * 2 + s2;
                            MMA16816F(acc[mi][nt], ah[mi], bh[s2 * 2], bh[s2 * 2 + 1]);
                            MMA16816F(acc[mi][nt], al[mi], bh[s2 * 2], bh[s2 * 2 + 1]);
                        }
                }
            }
        }

        // epilogue in registers: m3 gate + bias + relu, row-pool (acc[mi] vs acc[mi+2]),
        // col-pool via shfl_xor(4), m4 gate, write fp16 hi/lo p2
        int mtrow = mt * 8;
        int prg = mt * 4 + wm;
        #pragma unroll
        for (int mi = 0; mi < 2; mi++)
            #pragma unroll
            for (int nt = 0; nt < 4; nt++)
                #pragma unroll
                for (int e = 0; e < 4; e++) {
                    int col = mi * 16 + g + ((e >> 1) ? 8 : 0);
                    int occ = oc0 + nt * 8 + qu * 2 + (e & 1);
                    float bb = b2s[occ];
                    float v0 = sm[SM_M3 + (mtrow + 2 * wm) * 32 + col]
                               ? fmaxf(acc[mi][nt][e] + bb, 0.f) : 0.f;
                    float v1 = sm[SM_M3 + (mtrow + 2 * wm + 1) * 32 + col]
                               ? fmaxf(acc[mi + 2][nt][e] + bb, 0.f) : 0.f;
                    float v = fmaxf(v0, v1);
                    float vp = __shfl_xor_sync(0xffffffffu, v, 4);
                    if (!(g & 1)) {
                        float pooled = fmaxf(v, vp);
                        int pc = col >> 1;
                        if (!sm[SM_M4 + prg * 16 + pc]) pooled = 0.f;
                        __half hb = __float2half_rn(pooled);
                        __half lb = __float2half_rn(pooled - __half2float(hb));
                        size_t o = (size_t)b * 16384 + occ * 256 + prg * 16 + pc;
                        g_p2h[o] = hb;
                        g_p2l[o] = lb;
                    }
                }
    }
}

// ---------------- FC1 via mma.sync fp16 (3-term) ----------------
// smem: Ah 18432 | Al 18432 | Wh 18432 | Wl 18432 = 73728 (pitch 144B per 64-half row)
#define F1_AH 0
#define F1_AL 18432
#define F1_WH 36864
#define F1_WL 55296
#define F1_SMEM 73728

__global__ void __launch_bounds__(256) fc_init_kernel(const float* __restrict__ bfc1) {
    int i = blockIdx.x * 256 + threadIdx.x;
    if (i < BATCH * 128) g_h[i] = bfc1[i & 127];
}

// grid (2 M-tiles of 128, 64 k-chunks of 256), 256 threads
__global__ void __launch_bounds__(256, 2) fc1_mma_kernel(const float* __restrict__ Wfc1) {
    extern __shared__ char sm[];
    int t = threadIdx.x;
    int mtile = blockIdx.x, kc = blockIdx.y;
    int warp = t >> 5, lane = t & 31;
    uint32_t sb = s2u(sm);
    int wm = warp & 3, wn = warp >> 2;   // 4 M(32px) x 2 N(64oc)
    int g = lane >> 2, qu = lane & 3;
    int rowlane = lane & 15;
    int aKoff = (lane >= 16) ? 16 : 0;
    int grpB = lane >> 3;
    int ocoffB = ((grpB >> 1) << 3) + (lane & 7);
    int bKoff = (grpB & 1) * 16;

    float acc[2][8][4];
    #pragma unroll
    for (int mi = 0; mi < 2; mi++)
        #pragma unroll
        for (int nt = 0; nt < 8; nt++)
            #pragma unroll
            for (int e = 0; e < 4; e++) acc[mi][nt][e] = 0.f;

    const uint32_t* Ahg = (const uint32_t*)g_p2h;
    const uint32_t* Alg = (const uint32_t*)g_p2l;

    for (int sub = 0; sub < 4; sub++) {
        int k0 = kc * 256 + sub * 64;
        __syncthreads();
        for (int i = t; i < 4096; i += 256) {
            int row = i >> 5, w = i & 31;
            size_t gi = (size_t)(mtile * 128 + row) * 8192 + (k0 >> 1) + w;
            *(uint32_t*)(sm + F1_AH + row * 144 + w * 4) = Ahg[gi];
            *(uint32_t*)(sm + F1_AL + row * 144 + w * 4) = Alg[gi];
        }
        for (int i = t; i < 8192; i += 256) {
            int oc = i >> 6, kk = i & 63;
            float v = Wfc1[(size_t)oc * 16384 + k0 + kk];
            __half hb = __float2half_rn(v);
            __half lb = __float2half_rn(v - __half2float(hb));
            *(__half*)(sm + F1_WH + oc * 144 + kk * 2) = hb;
            *(__half*)(sm + F1_WL + oc * 144 + kk * 2) = lb;
        }
        __syncthreads();
        #pragma unroll
        for (int k16 = 0; k16 < 4; k16++) {
            uint32_t ah[2][4], al[2][4];
            #pragma unroll
            for (int mi = 0; mi < 2; mi++) {
                int row = wm * 32 + mi * 16 + rowlane;
                uint32_t addr = sb + F1_AH + (uint32_t)(row * 144 + k16 * 32 + aKoff);
                LDSM4(ah[mi], addr);
                LDSM4(al[mi], addr + 18432);
            }
            #pragma unroll
            for (int nb = 0; nb < 4; nb++) {
                uint32_t bh[4], bl[4];
                int oc0 = wn * 64 + nb * 16;
                uint32_t baddr = sb + F1_WH + (uint32_t)((oc0 + ocoffB) * 144 + k16 * 32 + bKoff);
                LDSM4(bh, baddr);
                LDSM4(bl, baddr + 18432);
                #pragma unroll
                for (int mi = 0; mi < 2; mi++)
                    #pragma unroll
                    for (int s2 = 0; s2 < 2; s2++) {
                        int nt = nb * 2 + s2;
                        MMA16816F(acc[mi][nt], ah[mi], bh[s2 * 2], bh[s2 * 2 + 1]);
                        MMA16816F(acc[mi][nt], al[mi], bh[s2 * 2], bh[s2 * 2 + 1]);
                        MMA16816F(acc[mi][nt], ah[mi], bl[s2 * 2], bl[s2 * 2 + 1]);
                    }
            }
        }
    }
    #pragma unroll
    for (int mi = 0; mi < 2; mi++)
        #pragma unroll
        for (int nt = 0; nt < 8; nt++)
            #pragma unroll
            for (int e = 0; e < 4; e++) {
                int row = mtile * 128 + wm * 32 + mi * 16 + g + ((e >> 1) ? 8 : 0);
                int col = wn * 64 + nt * 8 + qu * 2 + (e & 1);
                atomicAdd(&g_h[row * 128 + col], acc[mi][nt][e]);
            }
}

__global__ void __launch_bounds__(128) fc2_kernel(const float* __restrict__ Wfc2,
                                                  const float* __restrict__ bfc2,
                                                  float* __restrict__ out) {
    int b = blockIdx.x, t = threadIdx.x;
    __shared__ float hr[128];
    hr[t] = fmaxf(g_h[b * 128 + t], 0.f);
    __syncthreads();
    if (t < 10) {
        float s = bfc2[t];
        const float* w = Wfc2 + t * 128;
        #pragma unroll 8
        for (int k = 0; k < 128; k++) s += hr[k] * w[k];
        out[b * 10 + t] = s;
    }
}

// ---------------- launch ----------------
extern "C" void kernel_launch(void* const* d_in, const int* in_sizes, int n_in,
                              void* d_out, int out_size) {
    const float* x    = (const float*)d_in[0];
    const int*   cmap = (const int*)  d_in[1];
    const float* W1   = (const float*)d_in[2];
    const float* b1   = (const float*)d_in[3];
    const float* W2   = (const float*)d_in[4];
    const float* b2   = (const float*)d_in[5];
    const float* Wfc1 = (const float*)d_in[6];
    const float* bfc1 = (const float*)d_in[7];
    const float* Wfc2 = (const float*)d_in[8];
    const float* bfc2 = (const float*)d_in[9];
    float* out = (float*)d_out;

    cudaFuncSetAttribute(conv1_kernel, cudaFuncAttributeMaxDynamicSharedMemorySize, C1_SMEM);
    cudaFuncSetAttribute(conv2_mma_kernel, cudaFuncAttributeMaxDynamicSharedMemorySize, C2_SMEM);
    cudaFuncSetAttribute(fc1_mma_kernel, cudaFuncAttributeMaxDynamicSharedMemorySize, F1_SMEM);

    masks_kernel<<<BATCH, 256>>>(cmap);
    border_kernel<<<BATCH, 256>>>();
    conv1_kernel<<<BATCH, 256, C1_SMEM>>>(x, W1, b1);
    conv2_mma_kernel<<<BATCH * 2, 256, C2_SMEM>>>(W2, b2);
    fc_init_kernel<<<(BATCH * 128 + 255) / 256, 256>>>(bfc1);
    dim3 g1(2, 64);
    fc1_mma_kernel<<<g1, 256, F1_SMEM>>>(Wfc1);
    fc2_kernel<<<BATCH, 128>>>(Wfc2, bfc2, out);
}